// round 17
// baseline (speedup 1.0000x reference)
#include <cuda_runtime.h>
#include <cuda_bf16.h>
#include <math.h>
#include <stdint.h>

// ---------------- problem constants ----------------
#define BN    4096          // nodes (B*N)
#define NE    131072        // edges
#define DIMN  480           // 128 + 3*64 + 5*32
#define W3    192           // 3*MSG
#define RBFD  32
#define CUT   5.0f
#define NT    1024          // radial table resolution
#define TSTEP (CUT / (float)(NT - 1))
#define TSCALE ((float)(NT - 1) / CUT)

// ---------------- packed f32x2 helpers ----------------
__device__ __forceinline__ unsigned long long pack2(float lo, float hi) {
    unsigned long long r;
    asm("mov.b64 %0, {%1, %2};" : "=l"(r) : "f"(lo), "f"(hi));
    return r;
}
__device__ __forceinline__ void unpack2(unsigned long long v, float& lo, float& hi) {
    asm("mov.b64 {%0, %1}, %2;" : "=f"(lo), "=f"(hi) : "l"(v));
}
__device__ __forceinline__ void fma2(unsigned long long& d, unsigned long long a,
                                     unsigned long long b) {
    asm("fma.rn.f32x2 %0, %1, %2, %3;" : "=l"(d) : "l"(a), "l"(b), "l"(d));
}

// ---------------- scratch (device globals; no allocation) ----------------
__device__ float g_x[BN * DIMN];                   // node features
__device__ float g_P[BN * W3];                     // per-node projection x[:, :128] @ Wp
__device__ float g_m[BN * 576];                    // per-node segment sums
__device__ float g_sh8[(size_t)NE * 8];            // per-edge sh[1..8] (edge order, aligned)
__device__ float g_table[(size_t)3 * NT * W3];     // radial tables for all 3 blocks
__device__ float g_px[NE];                         // position-ordered table coordinate
__device__ int   g_psrc[NE];                       // position-ordered src node
__device__ float g_psh[(size_t)NE * 8];            // position-ordered sh[1..8]
__device__ int   g_cnt[BN];                        // zero-init at load; re-zeroed by scan
__device__ int   g_off[BN + 1];
__device__ int   g_cur[BN];
__device__ int   g_perm[NE];

// ---------------- fused setup: init (32 nodes/CTA) + geometry (sh only) + count ----------------
#define G_INIT 128
#define G_GEO  512
#define G_CNT  512
__global__ void __launch_bounds__(256) k_setup(const int* __restrict__ z,
                                               const float* __restrict__ mask,
                                               const float* __restrict__ z_emb,
                                               const float* __restrict__ W_in,
                                               const float* __restrict__ ew,
                                               const float* __restrict__ evec,
                                               const int* __restrict__ dst) {
    int bx = blockIdx.x;
    int t = threadIdx.x;
    if (bx < G_INIT) {
        __shared__ float sZ[32 * 128];
        __shared__ int   sZi[32];
        __shared__ float sMk[32];
        int n0 = bx * 32;
        if (t < 32) { sZi[t] = z[n0 + t]; sMk[t] = mask[n0 + t]; }
        __syncthreads();
        for (int q = t; q < 32 * 128; q += 256) {
            int nl = q >> 7, k = q & 127;
            sZ[q] = z_emb[sZi[nl] * 128 + k];
        }
        __syncthreads();
        int j = t & 127, g = t >> 7;
        float acc[16];
#pragma unroll
        for (int nn = 0; nn < 16; nn++) acc[nn] = 0.f;
#pragma unroll 4
        for (int k = 0; k < 128; k++) {
            float wv = W_in[k * 128 + j];
            const float* zr = &sZ[(g * 16) * 128 + k];
#pragma unroll
            for (int nn = 0; nn < 16; nn++) acc[nn] += zr[nn * 128] * wv;
        }
#pragma unroll
        for (int nn = 0; nn < 16; nn++) {
            int nl = g * 16 + nn;
            g_x[(size_t)(n0 + nl) * DIMN + j] = acc[nn] * sMk[nl];
        }
        for (int idx = t; idx < 32 * 352; idx += 256) {
            int nl = idx / 352, o = 128 + (idx - nl * 352);
            g_x[(size_t)(n0 + nl) * DIMN + o] = 0.f;
        }
    } else if (bx < G_INIT + G_GEO) {
        int e = (bx - G_INIT) * 256 + t;
        float len = ew[e];
        float inv = 1.f / fmaxf(len, 1e-8f);
        float x = evec[e * 3 + 0] * inv;
        float y = evec[e * 3 + 1] * inv;
        float zc = evec[e * 3 + 2] * inv;
        const float s3 = 1.7320508075688772f;
        const float s5 = 2.2360679774997896f;
        const float s15 = 3.872983346207417f;
        float4 f0, f1;
        f0.x = s3 * x; f0.y = s3 * y; f0.z = s3 * zc;
        f0.w = s15 * x * y;
        f1.x = s15 * y * zc;
        f1.y = 0.5f * s5 * (3.f * zc * zc - 1.f);
        f1.z = s15 * x * zc;
        f1.w = 0.5f * s15 * (x * x - y * y);
        float4* shp = (float4*)(g_sh8 + (size_t)e * 8);
        shp[0] = f0;
        shp[1] = f1;
    } else {
        int e = (bx - G_INIT - G_GEO) * 256 + t;
        atomicAdd(&g_cnt[dst[e]], 1);
    }
}

// ---------------- projnode body (block 0 only, inside k_aux) ----------------
__device__ __forceinline__ void projnode_body(float* sm, int cta, const float* __restrict__ Wpb) {
    float* sAT = sm;
    float* sWp = sm + 8704;
    int t = threadIdx.x;
    int n0 = cta * 64;

    {
        int i = t >> 2, q = t & 3;
        const float* xr = g_x + (size_t)(n0 + i) * DIMN + q * 32;
#pragma unroll
        for (int r = 0; r < 8; r++) {
            float4 v = *(const float4*)(xr + r * 4);
            int k = q * 32 + r * 4;
            sAT[(k + 0) * 68 + i] = v.x;
            sAT[(k + 1) * 68 + i] = v.y;
            sAT[(k + 2) * 68 + i] = v.z;
            sAT[(k + 3) * 68 + i] = v.w;
        }
    }
    for (int q = t; q < 6144; q += 256) {
        int k = q / 48, j4 = q - k * 48;
        int txp = j4 / 3, g = j4 - txp * 3;
        ((float4*)sWp)[(k * 3 + g) * 16 + txp] = ((const float4*)Wpb)[q];
    }
    __syncthreads();

    int tx = t & 15, ty = t >> 4;
    int i0 = ty * 4;
    unsigned long long acc2[4][6];
#pragma unroll
    for (int a = 0; a < 4; a++)
#pragma unroll
        for (int b = 0; b < 6; b++) acc2[a][b] = 0ull;

#pragma unroll 4
    for (int k = 0; k < 128; k++) {
        float4 a0 = *(const float4*)&sAT[k * 68 + i0];
        const float4* bbase = (const float4*)sWp + k * 48 + tx;
        float4 f0 = bbase[0];
        float4 f1 = bbase[16];
        float4 f2 = bbase[32];
        unsigned long long bb2[6];
        bb2[0] = pack2(f0.x, f0.y); bb2[1] = pack2(f0.z, f0.w);
        bb2[2] = pack2(f1.x, f1.y); bb2[3] = pack2(f1.z, f1.w);
        bb2[4] = pack2(f2.x, f2.y); bb2[5] = pack2(f2.z, f2.w);
        float av[4] = {a0.x, a0.y, a0.z, a0.w};
#pragma unroll
        for (int a = 0; a < 4; a++) {
            unsigned long long aa = pack2(av[a], av[a]);
#pragma unroll
            for (int b = 0; b < 6; b++) fma2(acc2[a][b], aa, bb2[b]);
        }
    }
    int j0 = tx * 12;
#pragma unroll
    for (int a = 0; a < 4; a++) {
        float accs[12];
#pragma unroll
        for (int b = 0; b < 6; b++) unpack2(acc2[a][b], accs[2 * b], accs[2 * b + 1]);
        float* pr = g_P + (size_t)(n0 + i0 + a) * W3 + j0;
#pragma unroll
        for (int g = 0; g < 3; g++) {
            float4 v;
            v.x = accs[g * 4 + 0]; v.y = accs[g * 4 + 1];
            v.z = accs[g * 4 + 2]; v.w = accs[g * 4 + 3];
            *(float4*)(pr + g * 4) = v;
        }
    }
}

// ---------------- table body: g_table[blk][r0+*] = fcut*(r+rb2) ----------------
__device__ __forceinline__ void table_body(float* sm, int cta,
                                           const float* __restrict__ rW1,
                                           const float* __restrict__ rb1,
                                           const float* __restrict__ rW2,
                                           const float* __restrict__ rb2) {
    float* sRbfT = sm;
    float* s_rW1 = sm + 2176;
    float* sHT   = sm + 4224;
    float* s_rW2 = sm + 8576;
    float* sFcut = sm + 20864;
    float* s_rb1 = sm + 20928;
    float* s_rb2 = sm + 20992;

    int t = threadIdx.x;
    const int per_blk = NT / 64;
    int blk = cta / per_blk;
    int r0 = (cta % per_blk) * 64;
    const float* rW1b = rW1 + blk * 32 * 64;
    const float* rb1b = rb1 + blk * 64;
    const float* rW2b = rW2 + blk * 64 * 192;
    const float* rb2b = rb2 + blk * 192;
    float* tbl = g_table + (size_t)blk * NT * W3;

    {
        int i = t >> 2, q = t & 3;
        float d = (float)(r0 + i) * TSTEP;
        float dm = fminf(d, CUT);
        const float width = CUT / 31.f;
#pragma unroll
        for (int r = 0; r < 8; r++) {
            int k = q * 8 + r;
            float c = CUT * (float)k / 31.f;
            float u = (dm - c) / width;
            sRbfT[k * 68 + i] = expf(-0.5f * u * u);
        }
    }
    for (int q = t; q < 512; q += 256)  ((float4*)s_rW1)[q] = ((const float4*)rW1b)[q];
    for (int q = t; q < 3072; q += 256) {
        int k = q / 48, j4 = q - k * 48;
        int txp = j4 / 3, g = j4 - txp * 3;
        ((float4*)s_rW2)[(k * 3 + g) * 16 + txp] = ((const float4*)rW2b)[q];
    }
    if (t < 64) {
        float d = (float)(r0 + t) * TSTEP;
        float tt = fminf(d / CUT, 1.f);
        sFcut[t] = 0.5f * (cosf(3.14159265358979323846f * tt) + 1.f);
        s_rb1[t] = rb1b[t];
    }
    if (t >= 64 && t < 256) s_rb2[t - 64] = rb2b[t - 64];
    __syncthreads();

    int tx = t & 15, ty = t >> 4;
    int i0 = ty * 4;

    {
        int c0 = tx * 4;
        unsigned long long hh2[4][2];
#pragma unroll
        for (int a = 0; a < 4; a++) { hh2[a][0] = 0ull; hh2[a][1] = 0ull; }
#pragma unroll 4
        for (int k = 0; k < 32; k++) {
            float4 a0 = *(const float4*)&sRbfT[k * 68 + i0];
            ulonglong2 bq = *(const ulonglong2*)&s_rW1[k * 64 + c0];
            float av[4] = {a0.x, a0.y, a0.z, a0.w};
#pragma unroll
            for (int a = 0; a < 4; a++) {
                unsigned long long aa = pack2(av[a], av[a]);
                fma2(hh2[a][0], aa, bq.x);
                fma2(hh2[a][1], aa, bq.y);
            }
        }
#pragma unroll
        for (int a = 0; a < 4; a++) {
            float hv[4];
            unpack2(hh2[a][0], hv[0], hv[1]);
            unpack2(hh2[a][1], hv[2], hv[3]);
#pragma unroll
            for (int b = 0; b < 4; b++) {
                float v = hv[b] + s_rb1[c0 + b];
                v = v / (1.f + expf(-v));      // silu
                sHT[(c0 + b) * 68 + (i0 + a)] = v;
            }
        }
    }
    __syncthreads();

    {
        unsigned long long acc2[4][6];
#pragma unroll
        for (int a = 0; a < 4; a++)
#pragma unroll
            for (int b = 0; b < 6; b++) acc2[a][b] = 0ull;
#pragma unroll 4
        for (int k = 0; k < 64; k++) {
            float4 a0 = *(const float4*)&sHT[k * 68 + i0];
            const float4* bbase = (const float4*)s_rW2 + k * 48 + tx;
            float4 f0 = bbase[0];
            float4 f1 = bbase[16];
            float4 f2 = bbase[32];
            unsigned long long bb2[6];
            bb2[0] = pack2(f0.x, f0.y); bb2[1] = pack2(f0.z, f0.w);
            bb2[2] = pack2(f1.x, f1.y); bb2[3] = pack2(f1.z, f1.w);
            bb2[4] = pack2(f2.x, f2.y); bb2[5] = pack2(f2.z, f2.w);
            float av[4] = {a0.x, a0.y, a0.z, a0.w};
#pragma unroll
            for (int a = 0; a < 4; a++) {
                unsigned long long aa = pack2(av[a], av[a]);
#pragma unroll
                for (int b = 0; b < 6; b++) fma2(acc2[a][b], aa, bb2[b]);
            }
        }
        int j0 = tx * 12;
        float rb[12];
#pragma unroll
        for (int b = 0; b < 12; b++) rb[b] = s_rb2[j0 + b];
#pragma unroll
        for (int a = 0; a < 4; a++) {
            float accs[12];
#pragma unroll
            for (int b = 0; b < 6; b++) unpack2(acc2[a][b], accs[2 * b], accs[2 * b + 1]);
            float fc = sFcut[i0 + a];
            float* outp = tbl + (size_t)(r0 + i0 + a) * W3 + j0;
#pragma unroll
            for (int g = 0; g < 3; g++) {
                float4 v;
                v.x = (accs[g * 4 + 0] + rb[g * 4 + 0]) * fc;
                v.y = (accs[g * 4 + 1] + rb[g * 4 + 1]) * fc;
                v.z = (accs[g * 4 + 2] + rb[g * 4 + 2]) * fc;
                v.w = (accs[g * 4 + 3] + rb[g * 4 + 3]) * fc;
                *(float4*)(outp + g * 4) = v;
            }
        }
    }
}

// ---------------- aux launch: CTA 0 scan, CTAs 1..TBL table, rest proj block 0 ----
#define TBL_CTAS (3 * (NT / 64))
#define AUX_SMEM_BYTES (33280 * 4)
__global__ void __launch_bounds__(256) k_aux(const float* __restrict__ Wp0,
                                             const float* __restrict__ rW1,
                                             const float* __restrict__ rb1,
                                             const float* __restrict__ rW2,
                                             const float* __restrict__ rb2) {
    extern __shared__ float sm[];
    int bx = blockIdx.x;
    int t = threadIdx.x;
    if (bx == 0) {
        __shared__ int part[256];
        int base = t * 16;
        int loc[16];
        int s = 0;
#pragma unroll
        for (int i = 0; i < 16; i++) { loc[i] = s; s += g_cnt[base + i]; }
        part[t] = s;
        __syncthreads();
        for (int off = 1; off < 256; off <<= 1) {
            int v = (t >= off) ? part[t - off] : 0;
            __syncthreads();
            part[t] += v;
            __syncthreads();
        }
        int pre = (t == 0) ? 0 : part[t - 1];
#pragma unroll
        for (int i = 0; i < 16; i++) {
            g_off[base + i] = pre + loc[i];
            g_cur[base + i] = pre + loc[i];
            g_cnt[base + i] = 0;
        }
        if (t == 255) g_off[BN] = part[255];
    } else if (bx <= TBL_CTAS) {
        table_body(sm, bx - 1, rW1, rb1, rW2, rb2);
    } else {
        projnode_body(sm, bx - 1 - TBL_CTAS, Wp0);
    }
}

__global__ void k_fill(const int* __restrict__ dst) {
    int e = blockIdx.x * 256 + threadIdx.x;
    if (e < NE) {
        int p = atomicAdd(&g_cur[dst[e]], 1);
        g_perm[p] = e;
    }
}

// ---------------- sort + gather: per-node warp sorts segment, then writes
// position-ordered (x, src, sh8) so k_seg streams with chain depth 1. ----------
#define SORT_CAP 512
__global__ void __launch_bounds__(256) k_sortgather(const float* __restrict__ ew,
                                                    const int* __restrict__ esrc) {
    __shared__ int sbuf[8 * SORT_CAP];
    int warp = threadIdx.x >> 5, lane = threadIdx.x & 31;
    int n = blockIdx.x * 8 + warp;
    int lo = g_off[n], hi = g_off[n + 1];
    int len = hi - lo;
    int* buf = sbuf + warp * SORT_CAP;
    if (len == 0) return;
    bool in_smem = (len <= SORT_CAP);
    if (len > 1) {
        if (in_smem) {
            for (int i = lane; i < len; i += 32) buf[i] = g_perm[lo + i];
            __syncwarp();
            for (int r = 0; r < len; r++) {
                int st = r & 1;
                for (int i = st + 2 * lane; i + 1 < len; i += 64) {
                    int a = buf[i], b = buf[i + 1];
                    if (a > b) { buf[i] = b; buf[i + 1] = a; }
                }
                __syncwarp();
            }
        } else if (lane == 0) {   // fallback, practically unreachable at Poisson(32)
            for (int i = lo + 1; i < hi; i++) {
                int key = g_perm[i];
                int j = i - 1;
                while (j >= lo && g_perm[j] > key) { g_perm[j + 1] = g_perm[j]; j--; }
                g_perm[j + 1] = key;
            }
        }
        __syncwarp();
    } else if (in_smem) {
        if (lane == 0) buf[0] = g_perm[lo];
        __syncwarp();
    }
    for (int i = lane; i < len; i += 32) {
        int e = in_smem ? buf[i] : g_perm[lo + i];
        int p = lo + i;
        g_px[p] = fminf(ew[e], CUT) * TSCALE;
        g_psrc[p] = esrc[e];
        const float4* shs = (const float4*)(g_sh8 + (size_t)e * 8);
        float4* shd = (float4*)(g_psh + (size_t)p * 8);
        shd[0] = shs[0];
        shd[1] = shs[1];
    }
}

// ---------------- fused segment sum (4 edge-lanes x 48 col-lanes, 2-way pipelined) --------
__global__ void __launch_bounds__(192) k_seg(const float* __restrict__ tbl) {
    __shared__ float sred[4 * 48 * 20];    // 15360 B
    int n = blockIdx.x;
    int t = threadIdx.x;
    int el = t / 48;
    int u  = t - el * 48;
    int lo = g_off[n], hi = g_off[n + 1];

    float acc[20];
#pragma unroll
    for (int i = 0; i < 20; i++) acc[i] = 0.f;

    const float4* tbl4 = (const float4*)tbl;
    const float4* P4 = (const float4*)g_P;
    const float4* psh4 = (const float4*)g_psh;

    auto accum = [&](int p, float4 w) {
        if (u < 16) {
            acc[0] += w.x; acc[1] += w.y; acc[2] += w.z; acc[3] += w.w;
        } else if (u < 32) {
            float4 f0 = psh4[(size_t)p * 2];
            float s0 = f0.x, s1 = f0.y, s2 = f0.z;
            acc[0] += w.x * s0; acc[1] += w.y * s0; acc[2] += w.z * s0; acc[3] += w.w * s0;
            acc[4] += w.x * s1; acc[5] += w.y * s1; acc[6] += w.z * s1; acc[7] += w.w * s1;
            acc[8] += w.x * s2; acc[9] += w.y * s2; acc[10] += w.z * s2; acc[11] += w.w * s2;
        } else {
            float4 f0 = psh4[(size_t)p * 2];
            float4 f1 = psh4[(size_t)p * 2 + 1];
            float sv[5] = {f0.w, f1.x, f1.y, f1.z, f1.w};
#pragma unroll
            for (int dd = 0; dd < 5; dd++) {
                float s = sv[dd];
                acc[dd * 4 + 0] += w.x * s;
                acc[dd * 4 + 1] += w.y * s;
                acc[dd * 4 + 2] += w.z * s;
                acc[dd * 4 + 3] += w.w * s;
            }
        }
    };

    int p = lo + el;
    for (; p + 4 < hi; p += 8) {
        float x0 = g_px[p],     x1 = g_px[p + 4];
        int  s0 = g_psrc[p],    s1 = g_psrc[p + 4];
        int i0 = (int)x0; if (i0 > NT - 2) i0 = NT - 2;
        int i1 = (int)x1; if (i1 > NT - 2) i1 = NT - 2;
        float f0 = x0 - (float)i0;
        float f1 = x1 - (float)i1;
        float4 t00 = tbl4[(size_t)i0 * 48 + u];
        float4 t01 = tbl4[(size_t)(i0 + 1) * 48 + u];
        float4 pv0 = P4[(size_t)s0 * 48 + u];
        float4 t10 = tbl4[(size_t)i1 * 48 + u];
        float4 t11 = tbl4[(size_t)(i1 + 1) * 48 + u];
        float4 pv1 = P4[(size_t)s1 * 48 + u];
        float4 w0, w1;
        w0.x = pv0.x * (t00.x + f0 * (t01.x - t00.x));
        w0.y = pv0.y * (t00.y + f0 * (t01.y - t00.y));
        w0.z = pv0.z * (t00.z + f0 * (t01.z - t00.z));
        w0.w = pv0.w * (t00.w + f0 * (t01.w - t00.w));
        w1.x = pv1.x * (t10.x + f1 * (t11.x - t10.x));
        w1.y = pv1.y * (t10.y + f1 * (t11.y - t10.y));
        w1.z = pv1.z * (t10.z + f1 * (t11.z - t10.z));
        w1.w = pv1.w * (t10.w + f1 * (t11.w - t10.w));
        accum(p, w0);
        accum(p + 4, w1);
    }
    if (p < hi) {
        float x = g_px[p];
        int src = g_psrc[p];
        int i = (int)x; if (i > NT - 2) i = NT - 2;
        float f = x - (float)i;
        float4 t0 = tbl4[(size_t)i * 48 + u];
        float4 t1 = tbl4[(size_t)(i + 1) * 48 + u];
        float4 pv = P4[(size_t)src * 48 + u];
        float4 w;
        w.x = pv.x * (t0.x + f * (t1.x - t0.x));
        w.y = pv.y * (t0.y + f * (t1.y - t0.y));
        w.z = pv.z * (t0.z + f * (t1.z - t0.z));
        w.w = pv.w * (t0.w + f * (t1.w - t0.w));
        accum(p, w);
    }

    float* my = sred + (size_t)t * 20;
#pragma unroll
    for (int i = 0; i < 20; i++) my[i] = acc[i];
    __syncthreads();

    if (el == 0) {
        float s[20];
#pragma unroll
        for (int i = 0; i < 20; i++)
            s[i] = sred[(size_t)u * 20 + i] + sred[(size_t)(48 + u) * 20 + i]
                 + sred[(size_t)(96 + u) * 20 + i] + sred[(size_t)(144 + u) * 20 + i];
        float* mr = g_m + (size_t)n * 576;
        if (u < 16) {
#pragma unroll
            for (int j = 0; j < 4; j++) mr[4 * u + j] = s[j];
        } else if (u < 32) {
            int c0 = 4 * u - 64;
#pragma unroll
            for (int j = 0; j < 4; j++)
#pragma unroll
                for (int dd = 0; dd < 3; dd++)
                    mr[64 + (c0 + j) * 3 + dd] = s[dd * 4 + j];
        } else {
            int c0 = 4 * u - 128;
#pragma unroll
            for (int j = 0; j < 4; j++)
#pragma unroll
                for (int dd = 0; dd < 5; dd++)
                    mr[256 + (c0 + j) * 5 + dd] = s[dd * 4 + j];
        }
    }
}

// ---------------- out + fused next-block projection (blocks 0,1) ----------------------
// x += rs*(m@Wo); then P_next = x_new[:, :128] @ Wp_next for this CTA's 16 nodes.
// smem floats: sW0 8192@0, sW1 4096@8192, sW2 2048@12288, sM 9216@14336, sXn 2048@23552
#define OUTP_SMEM_BYTES (25600 * 4)
__global__ void __launch_bounds__(256) k_out_proj(const float* __restrict__ Wo0b,
                                                  const float* __restrict__ Wo1b,
                                                  const float* __restrict__ Wo2b,
                                                  const float* __restrict__ res_scale, int b,
                                                  const float* __restrict__ Wp_next) {
    extern __shared__ float sm[];
    float* sW0 = sm;
    float* sW1 = sm + 8192;
    float* sW2 = sm + 12288;
    float* sM  = sm + 14336;
    float* sXn = sm + 23552;   // [16][128] new x0 rows
    int t = threadIdx.x;
    int n0 = blockIdx.x * 16;

    for (int q = t; q < 2048; q += 256) ((float4*)sW0)[q] = ((const float4*)Wo0b)[q];
    for (int q = t; q < 1024; q += 256) ((float4*)sW1)[q] = ((const float4*)Wo1b)[q];
    for (int q = t; q < 512;  q += 256) ((float4*)sW2)[q] = ((const float4*)Wo2b)[q];
    {
        const float4* mg = (const float4*)(g_m + (size_t)n0 * 576);
        for (int q = t; q < 2304; q += 256) ((float4*)sM)[q] = mg[q];
    }
    __syncthreads();

    float rs = res_scale[b];
    for (int idx = t; idx < 16 * 480; idx += 256) {
        int nl = idx / 480, o = idx - nl * 480;
        const float* m = sM + nl * 576;
        float u = 0.f;
        if (o < 128) {
#pragma unroll 8
            for (int k = 0; k < 64; k++) u += m[k] * sW0[k * 128 + o];
        } else if (o < 320) {
            int q = o - 128;
            int c = q / 3, d = q - c * 3;
#pragma unroll 8
            for (int k = 0; k < 64; k++) u += m[64 + k * 3 + d] * sW1[k * 64 + c];
        } else {
            int q = o - 320;
            int c = q / 5, d = q - c * 5;
#pragma unroll 8
            for (int k = 0; k < 64; k++) u += m[256 + k * 5 + d] * sW2[k * 32 + c];
        }
        float xn = g_x[(size_t)(n0 + nl) * DIMN + o] + rs * u;
        g_x[(size_t)(n0 + nl) * DIMN + o] = xn;
        if (o < 128) sXn[nl * 128 + o] = xn;
    }
    __syncthreads();

    // P_next for 16 nodes: 192 threads, tx=t%48 -> cols 4tx..4tx+3, ty=t/48 -> 4 nodes
    if (t < 192) {
        int tx = t % 48, ty = t / 48;
        unsigned long long acc2[4][2];
#pragma unroll
        for (int a = 0; a < 4; a++) { acc2[a][0] = 0ull; acc2[a][1] = 0ull; }
        const float4* Wp4 = (const float4*)Wp_next;
#pragma unroll 4
        for (int k = 0; k < 128; k++) {
            float4 wv = Wp4[k * 48 + tx];
            unsigned long long b0 = pack2(wv.x, wv.y);
            unsigned long long b1 = pack2(wv.z, wv.w);
#pragma unroll
            for (int a = 0; a < 4; a++) {
                float xv = sXn[(ty * 4 + a) * 128 + k];
                unsigned long long aa = pack2(xv, xv);
                fma2(acc2[a][0], aa, b0);
                fma2(acc2[a][1], aa, b1);
            }
        }
#pragma unroll
        for (int a = 0; a < 4; a++) {
            float4 v;
            unpack2(acc2[a][0], v.x, v.y);
            unpack2(acc2[a][1], v.z, v.w);
            ((float4*)(g_P + (size_t)(n0 + ty * 4 + a) * W3))[tx] = v;
        }
    }
}

// ---------------- final block: out + irrep RMS norm + mask fused -> out buffer ----------
#define OUT_SMEM_BYTES (23552 * 4)
__global__ void __launch_bounds__(256) k_out_norm(const float* __restrict__ Wo0b,
                                                  const float* __restrict__ Wo1b,
                                                  const float* __restrict__ Wo2b,
                                                  const float* __restrict__ res_scale,
                                                  const float* __restrict__ mask,
                                                  float* __restrict__ out) {
    extern __shared__ float sm[];
    float* sW0 = sm;
    float* sW1 = sm + 8192;
    float* sW2 = sm + 12288;
    float* sM  = sm + 14336;
    int t = threadIdx.x;
    int n0 = blockIdx.x * 16;

    for (int q = t; q < 2048; q += 256) ((float4*)sW0)[q] = ((const float4*)Wo0b)[q];
    for (int q = t; q < 1024; q += 256) ((float4*)sW1)[q] = ((const float4*)Wo1b)[q];
    for (int q = t; q < 512;  q += 256) ((float4*)sW2)[q] = ((const float4*)Wo2b)[q];
    {
        const float4* mg = (const float4*)(g_m + (size_t)n0 * 576);
        for (int q = t; q < 2304; q += 256) ((float4*)sM)[q] = mg[q];
    }
    __syncthreads();

    float rs = res_scale[2];
    int nl = t >> 4, ln = t & 15;
    int n = n0 + nl;
    const float* m = sM + nl * 576;
    const float* xr = g_x + (size_t)n * DIMN;

    float xv[30];
    float p0 = 0.f, p1 = 0.f, p2 = 0.f;
#pragma unroll
    for (int k = 0; k < 30; k++) {
        int o = ln + 16 * k;
        float u = 0.f;
        if (k < 8) {
#pragma unroll 8
            for (int kk = 0; kk < 64; kk++) u += m[kk] * sW0[kk * 128 + o];
        } else if (k < 20) {
            int q = o - 128;
            int c = q / 3, d = q - c * 3;
#pragma unroll 8
            for (int kk = 0; kk < 64; kk++) u += m[64 + kk * 3 + d] * sW1[kk * 64 + c];
        } else {
            int q = o - 320;
            int c = q / 5, d = q - c * 5;
#pragma unroll 8
            for (int kk = 0; kk < 64; kk++) u += m[256 + kk * 5 + d] * sW2[kk * 32 + c];
        }
        float xn = xr[o] + rs * u;
        xv[k] = xn;
        float sq = xn * xn;
        if (k < 8) p0 += sq;
        else if (k < 20) p1 += sq;
        else p2 += sq;
    }
#pragma unroll
    for (int off = 8; off >= 1; off >>= 1) {
        p0 += __shfl_xor_sync(0xffffffffu, p0, off, 16);
        p1 += __shfl_xor_sync(0xffffffffu, p1, off, 16);
        p2 += __shfl_xor_sync(0xffffffffu, p2, off, 16);
    }
    float inv0 = 1.f / sqrtf(p0 / 128.f + 1e-6f);
    float inv1 = 1.f / sqrtf(p1 / 64.f + 1e-6f);
    float inv2 = 1.f / sqrtf(p2 / 32.f + 1e-6f);
    float mm = mask[n];
    float* outr = out + (size_t)n * DIMN;
#pragma unroll
    for (int k = 0; k < 30; k++) {
        int o = ln + 16 * k;
        float inv = (k < 8) ? inv0 : ((k < 20) ? inv1 : inv2);
        outr[o] = xv[k] * inv * mm;
    }
}

// ---------------- launch ----------------
extern "C" void kernel_launch(void* const* d_in, const int* in_sizes, int n_in,
                              void* d_out, int out_size) {
    const int*   z         = (const int*)d_in[0];
    const float* mask      = (const float*)d_in[1];
    const int*   edge_src  = (const int*)d_in[2];
    const int*   edge_dst  = (const int*)d_in[3];
    const float* edge_w    = (const float*)d_in[4];
    const float* edge_vec  = (const float*)d_in[5];
    const float* z_emb     = (const float*)d_in[6];
    const float* W_in      = (const float*)d_in[7];
    const float* Wp        = (const float*)d_in[8];
    const float* rW1       = (const float*)d_in[9];
    const float* rb1       = (const float*)d_in[10];
    const float* rW2       = (const float*)d_in[11];
    const float* rb2       = (const float*)d_in[12];
    const float* Wo0       = (const float*)d_in[13];
    const float* Wo1       = (const float*)d_in[14];
    const float* Wo2       = (const float*)d_in[15];
    const float* res_scale = (const float*)d_in[16];
    float* out = (float*)d_out;

    cudaFuncSetAttribute(k_aux, cudaFuncAttributeMaxDynamicSharedMemorySize, AUX_SMEM_BYTES);
    cudaFuncSetAttribute(k_out_proj, cudaFuncAttributeMaxDynamicSharedMemorySize, OUTP_SMEM_BYTES);
    cudaFuncSetAttribute(k_out_norm, cudaFuncAttributeMaxDynamicSharedMemorySize, OUT_SMEM_BYTES);

    float* tbl_dev;
    cudaGetSymbolAddress((void**)&tbl_dev, g_table);

    k_setup<<<G_INIT + G_GEO + G_CNT, 256>>>(z, mask, z_emb, W_in, edge_w, edge_vec, edge_dst); // 0
    k_aux<<<1 + TBL_CTAS + 64, 256, AUX_SMEM_BYTES>>>(Wp, rW1, rb1, rW2, rb2);                   // 1
    k_fill<<<NE / 256, 256>>>(edge_dst);                                                         // 2
    k_sortgather<<<BN / 8, 256>>>(edge_w, edge_src);                                             // 3 <- ncu
    k_seg<<<BN, 192>>>(tbl_dev);                                                                 // 4
    k_out_proj<<<BN / 16, 256, OUTP_SMEM_BYTES>>>(Wo0, Wo1, Wo2, res_scale, 0,
                                                  Wp + 1 * 128 * 192);                           // 5
    k_seg<<<BN, 192>>>(tbl_dev + (size_t)1 * NT * W3);                                           // 6
    k_out_proj<<<BN / 16, 256, OUTP_SMEM_BYTES>>>(Wo0 + 1 * 64 * 128, Wo1 + 1 * 64 * 64,
                                                  Wo2 + 1 * 64 * 32, res_scale, 1,
                                                  Wp + 2 * 128 * 192);                           // 7
    k_seg<<<BN, 192>>>(tbl_dev + (size_t)2 * NT * W3);                                           // 8
    k_out_norm<<<BN / 16, 256, OUT_SMEM_BYTES>>>(Wo0 + 2 * 64 * 128, Wo1 + 2 * 64 * 64,
                                                 Wo2 + 2 * 64 * 32, res_scale, mask, out);       // 9
}